// round 7
// baseline (speedup 1.0000x reference)
#include <cuda_runtime.h>
#include <cuda_bf16.h>
#include <cuda_fp16.h>
#include <cstdint>
#include <math.h>

#define NN 50000
#define EE 800000
#define DD 96
#define MT 64                  // GEMM tile rows per block (4 warps/mat x 16 rows)
#define AS 104                 // A smem row stride in bf16 elems

// ---------------- scratch (device globals) ----------------
__device__ float g_y1[NN * DD];                 // x @ Wc1 (self path), fp32
__device__ __half g_h16[NN * DD];               // x @ Wc0 (neighbor path), fp16 for gather
__device__ __nv_bfloat16 g_xhi[NN * DD];        // layer-1 input, bf16 hi
__device__ __nv_bfloat16 g_xlo[NN * DD];        // layer-1 input, bf16 lo (residual)
__device__ int   g_rowptr[NN + 1];
// B fragments for mma.sync m16n8k16 (row.col):
// [layer][mat][hl: 0=hi,1=lo][kchunk 0..5][ntile 0..11][lane 0..31] -> {b0,b1}
__device__ uint2 g_Bfrag[2][2][2][6][12][32];
__device__ float g_biasA[2 * DD];               // b1 @ W2_top + b2
__device__ float g_biasB[2 * DD];               // b0 @ W2_bot (x in-degree)

static __device__ __forceinline__ unsigned short bf16_bits(__nv_bfloat16 h) {
    __nv_bfloat16_raw r = *(__nv_bfloat16_raw*)&h;
    return r.x;
}

// ---------------- row_ptr: lower_bound over sorted edge_dst ----------------
__global__ void build_rowptr(const int* __restrict__ dst, int E, int N) {
    int n = blockIdx.x * blockDim.x + threadIdx.x;
    if (n > N) return;
    int lo = 0, hi = E;
    while (lo < hi) { int mid = (lo + hi) >> 1; if (dst[mid] < n) lo = mid + 1; else hi = mid; }
    g_rowptr[n] = lo;
}

// ---------------- combine weights AND write mma fragments directly ----------------
__global__ void combine_w(const float* __restrict__ W0,
                          const float* __restrict__ W1,
                          const float* __restrict__ W2) {
    int r = blockIdx.x;        // k index 0..95
    int mat = blockIdx.y;      // 0 -> self(W1@W2_top), 1 -> neighbor(W0@W2_bot)
    int layer = blockIdx.z;
    int f = threadIdx.x;       // n index 0..95
    const float* Wa  = (mat == 0 ? W1 : W0) + layer * DD * DD + r * DD;
    const float* W2p = W2 + layer * 2 * DD * DD + (mat == 0 ? 0 : DD) * DD;
    float acc = 0.f;
#pragma unroll 4
    for (int k = 0; k < DD; k++) acc += Wa[k] * W2p[k * DD + f];
    __nv_bfloat16 hi = __float2bfloat16(acc);
    __nv_bfloat16 lo = __float2bfloat16(acc - __bfloat162float(hi));
    // fragment coords: k = kc*16 + tig*2 + jhi*8 + jlo ; n = nt*8 + gid ; lane = gid*4+tig
    int kc  = r >> 4, rem = r & 15;
    int tig = (rem >> 1) & 3, jhi = rem >> 3, jlo = rem & 1;
    int us  = jhi * 2 + jlo;           // ushort slot 0..3 within uint2
    int nt  = f >> 3, gid = f & 7;
    int lane = gid * 4 + tig;
    unsigned short* ph = (unsigned short*)&g_Bfrag[layer][mat][0][kc][nt][lane];
    unsigned short* pl = (unsigned short*)&g_Bfrag[layer][mat][1][kc][nt][lane];
    ph[us] = bf16_bits(hi);
    pl[us] = bf16_bits(lo);
}

__global__ void combine_b(const float* __restrict__ b0,
                          const float* __restrict__ b1,
                          const float* __restrict__ b2,
                          const float* __restrict__ W2) {
    int layer = blockIdx.x;
    int f = threadIdx.x;
    const float* W2p = W2 + layer * 2 * DD * DD;
    float accA = b2[layer * DD + f];
    float accB = 0.f;
#pragma unroll 4
    for (int k = 0; k < DD; k++) {
        accA += b1[layer * DD + k] * W2p[k * DD + f];
        accB += b0[layer * DD + k] * W2p[(DD + k) * DD + f];
    }
    g_biasA[layer * DD + f] = accA;
    g_biasB[layer * DD + f] = accB;
}

// ---------------- HMMA dual GEMM, warp-specialized by matrix ----------------
// 256 threads = 8 warps. Warps 0-3 -> mat0 (g_y1, fp32), warps 4-7 -> mat1
// (g_h16, fp16). Each warp owns 16 rows of a 64-row tile; exactly one
// 48-accumulator set live per thread (no mat loop -> no spills).
__global__ __launch_bounds__(256) void tensor_gemm(const float* __restrict__ x32,
                                                   int layer, int N) {
    extern __shared__ __nv_bfloat16 sm[];
    __nv_bfloat16* sHi = sm;
    __nv_bfloat16* sLo = sm + MT * AS;
    const int tid  = threadIdx.x;
    const int row0 = blockIdx.x * MT;

    // ---- fill A tile (64 rows x 96), split fp32 -> bf16 hi/lo ----
#pragma unroll
    for (int i = 0; i < 6; i++) {           // 64*24 chunks / 256 threads
        int idx = tid + i * 256;
        int m = idx / 24, c4 = idx % 24;
        int k = c4 * 4;
        int row = row0 + m;
        uint32_t h01 = 0, h23 = 0, l01 = 0, l23 = 0;
        if (row < N) {
            if (layer == 0) {
                float4 v = ((const float4*)(x32 + (size_t)row * DD))[c4];
                __nv_bfloat16 h0 = __float2bfloat16(v.x), h1 = __float2bfloat16(v.y);
                __nv_bfloat16 h2 = __float2bfloat16(v.z), h3 = __float2bfloat16(v.w);
                h01 = (uint32_t)bf16_bits(h0) | ((uint32_t)bf16_bits(h1) << 16);
                h23 = (uint32_t)bf16_bits(h2) | ((uint32_t)bf16_bits(h3) << 16);
                l01 = (uint32_t)bf16_bits(__float2bfloat16(v.x - __bfloat162float(h0)))
                    | ((uint32_t)bf16_bits(__float2bfloat16(v.y - __bfloat162float(h1))) << 16);
                l23 = (uint32_t)bf16_bits(__float2bfloat16(v.z - __bfloat162float(h2)))
                    | ((uint32_t)bf16_bits(__float2bfloat16(v.w - __bfloat162float(h3))) << 16);
            } else {
                uint2 th = *(const uint2*)(g_xhi + (size_t)row * DD + k);
                uint2 tl = *(const uint2*)(g_xlo + (size_t)row * DD + k);
                h01 = th.x; h23 = th.y; l01 = tl.x; l23 = tl.y;
            }
        }
        *(uint32_t*)&sHi[m * AS + k]     = h01;
        *(uint32_t*)&sHi[m * AS + k + 2] = h23;
        *(uint32_t*)&sLo[m * AS + k]     = l01;
        *(uint32_t*)&sLo[m * AS + k + 2] = l23;
    }
    __syncthreads();

    const int warp = tid >> 5, lane = tid & 31;
    const int gid = lane >> 2, tig = lane & 3;
    const int mat = warp >> 2;              // 0 or 1
    const int rbase = (warp & 3) * 16;

    float c[12][4];
#pragma unroll
    for (int nt = 0; nt < 12; nt++) { c[nt][0] = c[nt][1] = c[nt][2] = c[nt][3] = 0.f; }

#pragma unroll
    for (int span = 0; span < 3; span++) {
        const __nv_bfloat16* As = (span == 2) ? sLo : sHi;
        const int Bhl = (span == 1) ? 1 : 0;
#pragma unroll 1
        for (int kc = 0; kc < 6; kc++) {
            const int k0 = kc * 16 + tig * 2;
            uint32_t a0 = *(const uint32_t*)&As[(rbase + gid) * AS + k0];
            uint32_t a1 = *(const uint32_t*)&As[(rbase + gid + 8) * AS + k0];
            uint32_t a2 = *(const uint32_t*)&As[(rbase + gid) * AS + k0 + 8];
            uint32_t a3 = *(const uint32_t*)&As[(rbase + gid + 8) * AS + k0 + 8];
            const uint2* bp = &g_Bfrag[layer][mat][Bhl][kc][0][lane];
#pragma unroll
            for (int nt = 0; nt < 12; nt++) {
                uint2 b = __ldg(&bp[nt * 32]);
                asm volatile(
                    "mma.sync.aligned.m16n8k16.row.col.f32.bf16.bf16.f32 "
                    "{%0,%1,%2,%3}, {%4,%5,%6,%7}, {%8,%9}, {%0,%1,%2,%3};"
                    : "+f"(c[nt][0]), "+f"(c[nt][1]), "+f"(c[nt][2]), "+f"(c[nt][3])
                    : "r"(a0), "r"(a1), "r"(a2), "r"(a3), "r"(b.x), "r"(b.y));
            }
        }
    }

    // ---- epilogue ----
    const int r0 = row0 + rbase + gid;
    const int r1 = r0 + 8;
    if (mat == 0) {
#pragma unroll
        for (int nt = 0; nt < 12; nt++) {
            int col = nt * 8 + tig * 2;
            if (r0 < N) *(float2*)&g_y1[(size_t)r0 * DD + col] = make_float2(c[nt][0], c[nt][1]);
            if (r1 < N) *(float2*)&g_y1[(size_t)r1 * DD + col] = make_float2(c[nt][2], c[nt][3]);
        }
    } else {
#pragma unroll
        for (int nt = 0; nt < 12; nt++) {
            int col = nt * 8 + tig * 2;
            if (r0 < N) *(__half2*)&g_h16[(size_t)r0 * DD + col] = __floats2half2_rn(c[nt][0], c[nt][1]);
            if (r1 < N) *(__half2*)&g_h16[(size_t)r1 * DD + col] = __floats2half2_rn(c[nt][2], c[nt][3]);
        }
    }
}

// ---------------- aggregation + bias + unbiased-std normalize ----------------
// One warp per node; lane owns features {l, l+32, l+64}. fp16 gather.
__global__ __launch_bounds__(256) void agg_norm(const int* __restrict__ esrc,
                                                float* __restrict__ outF,
                                                int layer, int mode, int N) {
    int warp = (blockIdx.x * blockDim.x + threadIdx.x) >> 5;
    int lane = threadIdx.x & 31;
    if (warp >= N) return;
    const int node = warp;
    const int beg = g_rowptr[node];
    const int end = g_rowptr[node + 1];
    const float* bA = g_biasA + layer * DD;
    const float* bB = g_biasB + layer * DD;
    const float deg = (float)(end - beg);
    const float* yr = g_y1 + (size_t)node * DD;

    float a0 = yr[lane]      + bA[lane]      + deg * bB[lane];
    float a1 = yr[lane + 32] + bA[lane + 32] + deg * bB[lane + 32];
    float a2 = yr[lane + 64] + bA[lane + 64] + deg * bB[lane + 64];

    int e = beg;
    for (; e + 4 <= end; e += 4) {
        int s0 = __ldg(&esrc[e]);
        int s1 = __ldg(&esrc[e + 1]);
        int s2 = __ldg(&esrc[e + 2]);
        int s3 = __ldg(&esrc[e + 3]);
        const __half* h0 = g_h16 + (size_t)s0 * DD;
        const __half* h1 = g_h16 + (size_t)s1 * DD;
        const __half* h2 = g_h16 + (size_t)s2 * DD;
        const __half* h3 = g_h16 + (size_t)s3 * DD;
        float t00 = __half2float(__ldg(&h0[lane]));
        float t01 = __half2float(__ldg(&h0[lane + 32]));
        float t02 = __half2float(__ldg(&h0[lane + 64]));
        float t10 = __half2float(__ldg(&h1[lane]));
        float t11 = __half2float(__ldg(&h1[lane + 32]));
        float t12 = __half2float(__ldg(&h1[lane + 64]));
        float t20 = __half2float(__ldg(&h2[lane]));
        float t21 = __half2float(__ldg(&h2[lane + 32]));
        float t22 = __half2float(__ldg(&h2[lane + 64]));
        float t30 = __half2float(__ldg(&h3[lane]));
        float t31 = __half2float(__ldg(&h3[lane + 32]));
        float t32 = __half2float(__ldg(&h3[lane + 64]));
        a0 += (t00 + t10) + (t20 + t30);
        a1 += (t01 + t11) + (t21 + t31);
        a2 += (t02 + t12) + (t22 + t32);
    }
    for (; e < end; e++) {
        int s = __ldg(&esrc[e]);
        const __half* hr = g_h16 + (size_t)s * DD;
        a0 += __half2float(__ldg(&hr[lane]));
        a1 += __half2float(__ldg(&hr[lane + 32]));
        a2 += __half2float(__ldg(&hr[lane + 64]));
    }

    float sum = a0 + a1 + a2;
#pragma unroll
    for (int o = 16; o; o >>= 1) sum += __shfl_xor_sync(0xffffffffu, sum, o);
    float mean = sum * (1.0f / 96.0f);
    float d0 = a0 - mean, d1 = a1 - mean, d2 = a2 - mean;
    float sq = d0 * d0 + d1 * d1 + d2 * d2;
#pragma unroll
    for (int o = 16; o; o >>= 1) sq += __shfl_xor_sync(0xffffffffu, sq, o);
    float inv = rsqrtf(sq * (1.0f / 95.0f));

    float v0 = a0 * inv, v1 = a1 * inv, v2 = a2 * inv;
    if (mode == 1) {
        float* orow = outF + (size_t)node * DD;
        orow[lane] = v0; orow[lane + 32] = v1; orow[lane + 64] = v2;
    } else {
        __nv_bfloat16 h0 = __float2bfloat16(v0);
        __nv_bfloat16 h1 = __float2bfloat16(v1);
        __nv_bfloat16 h2 = __float2bfloat16(v2);
        size_t base = (size_t)node * DD;
        g_xhi[base + lane]      = h0;
        g_xhi[base + lane + 32] = h1;
        g_xhi[base + lane + 64] = h2;
        g_xlo[base + lane]      = __float2bfloat16(v0 - __bfloat162float(h0));
        g_xlo[base + lane + 32] = __float2bfloat16(v1 - __bfloat162float(h1));
        g_xlo[base + lane + 64] = __float2bfloat16(v2 - __bfloat162float(h2));
    }
}

// ---------------- host ----------------
extern "C" void kernel_launch(void* const* d_in, const int* in_sizes, int n_in,
                              void* d_out, int out_size) {
    const float* x   = (const float*)d_in[0];
    const float* W0  = (const float*)d_in[1];
    const float* b0  = (const float*)d_in[2];
    const float* W1  = (const float*)d_in[3];
    const float* b1  = (const float*)d_in[4];
    const float* W2  = (const float*)d_in[5];
    const float* b2  = (const float*)d_in[6];
    const int* esrc  = (const int*)d_in[7];
    const int* edst  = (const int*)d_in[8];
    float* out = (float*)d_out;

    const int N = in_sizes[0] / DD;
    const int E = in_sizes[7];

    const int smem_bytes = 2 * MT * AS * (int)sizeof(__nv_bfloat16);   // 26624
    cudaFuncSetAttribute(tensor_gemm, cudaFuncAttributeMaxDynamicSharedMemorySize, smem_bytes);

    build_rowptr<<<(N + 1 + 255) / 256, 256>>>(edst, E, N);
    combine_w<<<dim3(DD, 2, 2), DD>>>(W0, W1, W2);
    combine_b<<<2, DD>>>(b0, b1, b2, W2);

    const int gemm_grid = (N + MT - 1) / MT;
    const int agg_grid  = (N * 32 + 255) / 256;

    // layer 0: x fp32 -> GEMM -> agg_norm writes bf16 hi/lo
    tensor_gemm<<<gemm_grid, 256, smem_bytes>>>(x, 0, N);
    agg_norm<<<agg_grid, 256>>>(esrc, nullptr, 0, 0, N);

    // layer 1: bf16 hi/lo -> GEMM -> agg_norm writes fp32 out
    tensor_gemm<<<gemm_grid, 256, smem_bytes>>>(nullptr, 1, N);
    agg_norm<<<agg_grid, 256>>>(esrc, out, 1, 1, N);
}

// round 8
// speedup vs baseline: 1.3327x; 1.3327x over previous
#include <cuda_runtime.h>
#include <cuda_bf16.h>
#include <cuda_fp16.h>
#include <cstdint>
#include <math.h>

#define NN 50000
#define EE 800000
#define DD 96
#define MT 64                  // GEMM tile rows per block (4 warps/mat x 16 rows)
#define AS 104                 // A smem row stride in fp16 elems

// ---------------- scratch (device globals) ----------------
__device__ float g_y1[NN * DD];                 // x @ Wc1 (self path), fp32
__device__ __half g_h16[NN * DD];               // x @ Wc0 (neighbor path), fp16 gather
__device__ __half g_xh16[NN * DD];              // layer-1 input, fp16
__device__ int   g_rowptr[NN + 1];
// B fragments for mma.sync m16n8k16 (row.col), fp16:
// [layer][mat][hl: 0=hi,1=lo][kchunk 0..5][ntile 0..11][lane 0..31] -> {b0,b1}
__device__ uint2 g_Bfrag[2][2][2][6][12][32];
__device__ float g_biasA[2 * DD];               // b1 @ W2_top + b2
__device__ float g_biasB[2 * DD];               // b0 @ W2_bot (x in-degree)

static __device__ __forceinline__ unsigned short h16_bits(__half h) {
    __half_raw r = *(__half_raw*)&h;
    return r.x;
}

// ---------------- row_ptr: lower_bound over sorted edge_dst ----------------
__global__ void build_rowptr(const int* __restrict__ dst, int E, int N) {
    int n = blockIdx.x * blockDim.x + threadIdx.x;
    if (n > N) return;
    int lo = 0, hi = E;
    while (lo < hi) { int mid = (lo + hi) >> 1; if (dst[mid] < n) lo = mid + 1; else hi = mid; }
    g_rowptr[n] = lo;
}

// ---------------- combine weights AND write fp16 hi/lo mma fragments ----------------
__global__ void combine_w(const float* __restrict__ W0,
                          const float* __restrict__ W1,
                          const float* __restrict__ W2) {
    int r = blockIdx.x;        // k index 0..95
    int mat = blockIdx.y;      // 0 -> self(W1@W2_top), 1 -> neighbor(W0@W2_bot)
    int layer = blockIdx.z;
    int f = threadIdx.x;       // n index 0..95
    const float* Wa  = (mat == 0 ? W1 : W0) + layer * DD * DD + r * DD;
    const float* W2p = W2 + layer * 2 * DD * DD + (mat == 0 ? 0 : DD) * DD;
    float acc = 0.f;
#pragma unroll 4
    for (int k = 0; k < DD; k++) acc += Wa[k] * W2p[k * DD + f];
    __half hi = __float2half_rn(acc);
    __half lo = __float2half_rn(acc - __half2float(hi));
    // fragment coords: k = kc*16 + tig*2 + jhi*8 + jlo ; n = nt*8 + gid ; lane = gid*4+tig
    int kc  = r >> 4, rem = r & 15;
    int tig = (rem >> 1) & 3, jhi = rem >> 3, jlo = rem & 1;
    int us  = jhi * 2 + jlo;           // ushort slot 0..3 within uint2
    int nt  = f >> 3, gid = f & 7;
    int lane = gid * 4 + tig;
    unsigned short* ph = (unsigned short*)&g_Bfrag[layer][mat][0][kc][nt][lane];
    unsigned short* pl = (unsigned short*)&g_Bfrag[layer][mat][1][kc][nt][lane];
    ph[us] = h16_bits(hi);
    pl[us] = h16_bits(lo);
}

__global__ void combine_b(const float* __restrict__ b0,
                          const float* __restrict__ b1,
                          const float* __restrict__ b2,
                          const float* __restrict__ W2) {
    int layer = blockIdx.x;
    int f = threadIdx.x;
    const float* W2p = W2 + layer * 2 * DD * DD;
    float accA = b2[layer * DD + f];
    float accB = 0.f;
#pragma unroll 4
    for (int k = 0; k < DD; k++) {
        accA += b1[layer * DD + k] * W2p[k * DD + f];
        accB += b0[layer * DD + k] * W2p[(DD + k) * DD + f];
    }
    g_biasA[layer * DD + f] = accA;
    g_biasB[layer * DD + f] = accB;
}

// ---------------- HMMA dual GEMM, warp-specialized by matrix ----------------
// 256 threads = 8 warps. Warps 0-3 -> mat0 (g_y1, fp32), warps 4-7 -> mat1
// (g_h16, fp16). A single fp16; W in 2 fp16 terms (hi+lo). 12 kc-iters/warp.
__global__ __launch_bounds__(256) void tensor_gemm(const float* __restrict__ x32,
                                                   int layer, int N) {
    extern __shared__ __half sm[];
    __half* sA = sm;
    const int tid  = threadIdx.x;
    const int row0 = blockIdx.x * MT;

    // ---- fill A tile (64 rows x 96) fp16 ----
#pragma unroll
    for (int i = 0; i < 6; i++) {           // 64*24 chunks / 256 threads
        int idx = tid + i * 256;
        int m = idx / 24, c4 = idx % 24;
        int k = c4 * 4;
        int row = row0 + m;
        uint2 hv = make_uint2(0u, 0u);
        if (row < N) {
            if (layer == 0) {
                float4 v = ((const float4*)(x32 + (size_t)row * DD))[c4];
                __half2 p0 = __floats2half2_rn(v.x, v.y);
                __half2 p1 = __floats2half2_rn(v.z, v.w);
                hv.x = *(uint32_t*)&p0;
                hv.y = *(uint32_t*)&p1;
            } else {
                hv = *(const uint2*)(g_xh16 + (size_t)row * DD + k);
            }
        }
        *(uint2*)&sA[m * AS + k] = hv;
    }
    __syncthreads();

    const int warp = tid >> 5, lane = tid & 31;
    const int gid = lane >> 2, tig = lane & 3;
    const int mat = warp >> 2;              // 0 or 1
    const int rbase = (warp & 3) * 16;

    float c[12][4];
#pragma unroll
    for (int nt = 0; nt < 12; nt++) { c[nt][0] = c[nt][1] = c[nt][2] = c[nt][3] = 0.f; }

#pragma unroll
    for (int span = 0; span < 2; span++) {  // span0: W_hi, span1: W_lo
#pragma unroll
        for (int kc = 0; kc < 6; kc++) {
            const int k0 = kc * 16 + tig * 2;
            uint32_t a0 = *(const uint32_t*)&sA[(rbase + gid) * AS + k0];
            uint32_t a1 = *(const uint32_t*)&sA[(rbase + gid + 8) * AS + k0];
            uint32_t a2 = *(const uint32_t*)&sA[(rbase + gid) * AS + k0 + 8];
            uint32_t a3 = *(const uint32_t*)&sA[(rbase + gid + 8) * AS + k0 + 8];
            const uint2* bp = &g_Bfrag[layer][mat][span][kc][0][lane];
#pragma unroll
            for (int nt = 0; nt < 12; nt++) {
                uint2 b = __ldg(&bp[nt * 32]);
                asm volatile(
                    "mma.sync.aligned.m16n8k16.row.col.f32.f16.f16.f32 "
                    "{%0,%1,%2,%3}, {%4,%5,%6,%7}, {%8,%9}, {%0,%1,%2,%3};"
                    : "+f"(c[nt][0]), "+f"(c[nt][1]), "+f"(c[nt][2]), "+f"(c[nt][3])
                    : "r"(a0), "r"(a1), "r"(a2), "r"(a3), "r"(b.x), "r"(b.y));
            }
        }
    }

    // ---- epilogue ----
    const int r0 = row0 + rbase + gid;
    const int r1 = r0 + 8;
    if (mat == 0) {
#pragma unroll
        for (int nt = 0; nt < 12; nt++) {
            int col = nt * 8 + tig * 2;
            if (r0 < N) *(float2*)&g_y1[(size_t)r0 * DD + col] = make_float2(c[nt][0], c[nt][1]);
            if (r1 < N) *(float2*)&g_y1[(size_t)r1 * DD + col] = make_float2(c[nt][2], c[nt][3]);
        }
    } else {
#pragma unroll
        for (int nt = 0; nt < 12; nt++) {
            int col = nt * 8 + tig * 2;
            if (r0 < N) *(__half2*)&g_h16[(size_t)r0 * DD + col] = __floats2half2_rn(c[nt][0], c[nt][1]);
            if (r1 < N) *(__half2*)&g_h16[(size_t)r1 * DD + col] = __floats2half2_rn(c[nt][2], c[nt][3]);
        }
    }
}

// ---------------- aggregation + bias + unbiased-std normalize ----------------
// One warp per node; lane owns features {l, l+32, l+64}. fp16 gather, 8-edge batch.
__global__ __launch_bounds__(256) void agg_norm(const int* __restrict__ esrc,
                                                float* __restrict__ outF,
                                                int layer, int mode, int N) {
    int warp = (blockIdx.x * blockDim.x + threadIdx.x) >> 5;
    int lane = threadIdx.x & 31;
    if (warp >= N) return;
    const int node = warp;
    const int beg = g_rowptr[node];
    const int end = g_rowptr[node + 1];
    const float* bA = g_biasA + layer * DD;
    const float* bB = g_biasB + layer * DD;
    const float deg = (float)(end - beg);
    const float* yr = g_y1 + (size_t)node * DD;

    float a0 = yr[lane]      + bA[lane]      + deg * bB[lane];
    float a1 = yr[lane + 32] + bA[lane + 32] + deg * bB[lane + 32];
    float a2 = yr[lane + 64] + bA[lane + 64] + deg * bB[lane + 64];

    int e = beg;
    for (; e + 8 <= end; e += 8) {
        const __half* hp[8];
#pragma unroll
        for (int j = 0; j < 8; j++) hp[j] = g_h16 + (size_t)__ldg(&esrc[e + j]) * DD;
        float t0 = 0.f, t1 = 0.f, t2 = 0.f;
        float u0 = 0.f, u1 = 0.f, u2 = 0.f;
#pragma unroll
        for (int j = 0; j < 8; j += 2) {
            t0 += __half2float(__ldg(&hp[j][lane]));
            t1 += __half2float(__ldg(&hp[j][lane + 32]));
            t2 += __half2float(__ldg(&hp[j][lane + 64]));
            u0 += __half2float(__ldg(&hp[j + 1][lane]));
            u1 += __half2float(__ldg(&hp[j + 1][lane + 32]));
            u2 += __half2float(__ldg(&hp[j + 1][lane + 64]));
        }
        a0 += t0 + u0; a1 += t1 + u1; a2 += t2 + u2;
    }
    for (; e < end; e++) {
        int s = __ldg(&esrc[e]);
        const __half* hr = g_h16 + (size_t)s * DD;
        a0 += __half2float(__ldg(&hr[lane]));
        a1 += __half2float(__ldg(&hr[lane + 32]));
        a2 += __half2float(__ldg(&hr[lane + 64]));
    }

    float sum = a0 + a1 + a2;
#pragma unroll
    for (int o = 16; o; o >>= 1) sum += __shfl_xor_sync(0xffffffffu, sum, o);
    float mean = sum * (1.0f / 96.0f);
    float d0 = a0 - mean, d1 = a1 - mean, d2 = a2 - mean;
    float sq = d0 * d0 + d1 * d1 + d2 * d2;
#pragma unroll
    for (int o = 16; o; o >>= 1) sq += __shfl_xor_sync(0xffffffffu, sq, o);
    float inv = rsqrtf(sq * (1.0f / 95.0f));

    float v0 = a0 * inv, v1 = a1 * inv, v2 = a2 * inv;
    if (mode == 1) {
        float* orow = outF + (size_t)node * DD;
        orow[lane] = v0; orow[lane + 32] = v1; orow[lane + 64] = v2;
    } else {
        size_t base = (size_t)node * DD;
        g_xh16[base + lane]      = __float2half_rn(v0);
        g_xh16[base + lane + 32] = __float2half_rn(v1);
        g_xh16[base + lane + 64] = __float2half_rn(v2);
    }
}

// ---------------- host ----------------
extern "C" void kernel_launch(void* const* d_in, const int* in_sizes, int n_in,
                              void* d_out, int out_size) {
    const float* x   = (const float*)d_in[0];
    const float* W0  = (const float*)d_in[1];
    const float* b0  = (const float*)d_in[2];
    const float* W1  = (const float*)d_in[3];
    const float* b1  = (const float*)d_in[4];
    const float* W2  = (const float*)d_in[5];
    const float* b2  = (const float*)d_in[6];
    const int* esrc  = (const int*)d_in[7];
    const int* edst  = (const int*)d_in[8];
    float* out = (float*)d_out;

    const int N = in_sizes[0] / DD;
    const int E = in_sizes[7];

    const int smem_bytes = MT * AS * (int)sizeof(__half);   // 13312
    cudaFuncSetAttribute(tensor_gemm, cudaFuncAttributeMaxDynamicSharedMemorySize, smem_bytes);

    build_rowptr<<<(N + 1 + 255) / 256, 256>>>(edst, E, N);
    combine_w<<<dim3(DD, 2, 2), DD>>>(W0, W1, W2);
    combine_b<<<2, DD>>>(b0, b1, b2, W2);

    const int gemm_grid = (N + MT - 1) / MT;
    const int agg_grid  = (N * 32 + 255) / 256;

    // layer 0: x fp32 -> GEMM -> agg_norm writes fp16 x
    tensor_gemm<<<gemm_grid, 256, smem_bytes>>>(x, 0, N);
    agg_norm<<<agg_grid, 256>>>(esrc, nullptr, 0, 0, N);

    // layer 1: fp16 x -> GEMM -> agg_norm writes fp32 out
    tensor_gemm<<<gemm_grid, 256, smem_bytes>>>(nullptr, 1, N);
    agg_norm<<<agg_grid, 256>>>(esrc, out, 1, 1, N);
}